// round 1
// baseline (speedup 1.0000x reference)
#include <cuda_runtime.h>
#include <cuda_bf16.h>
#include <math.h>

// Problem constants
#define NN 50000
#define EE 800000
#define FF 2
#define DD 2
#define HH 64
#define TT 12
#define HZ 12

// ---------------- scratch (static device globals; no allocation) ----------------
__device__ __align__(256) int   g_deg[NN];
__device__ __align__(256) int   g_rowptr[NN + 1];
__device__ __align__(256) int   g_cursor[NN];
__device__ __align__(256) int   g_colsrc[EE];
__device__ __align__(256) float g_h0[NN * HH];
__device__ __align__(256) float g_h1[NN * HH];
__device__ __align__(256) float g_hrz[NN * 2 * HH];
__device__ __align__(256) float g_hc[NN * HH];
__device__ __align__(256) float g_el0[NN];
__device__ __align__(256) float g_el1[NN];
__device__ __align__(256) float g_er0[NN];
__device__ __align__(256) float g_er1[NN];
__device__ __align__(256) float g_prerz[NN * 2 * HH];
__device__ __align__(256) float g_prec[NN * HH];
__device__ __align__(256) float g_zbuf[NN * HH];
__device__ __align__(256) float g_rh[NN * HH];
__device__ __align__(256) float g_decin[NN * DD];

// ---------------- small utility kernels ----------------
__global__ void k_zero_f(float* p, int n) {
    int i = blockIdx.x * blockDim.x + threadIdx.x;
    if (i < n) p[i] = 0.f;
}
__global__ void k_zero_i(int* p, int n) {
    int i = blockIdx.x * blockDim.x + threadIdx.x;
    if (i < n) p[i] = 0;
}

// ---------------- CSR build ----------------
__global__ void k_hist(const int* __restrict__ dst) {
    int e = blockIdx.x * blockDim.x + threadIdx.x;
    if (e < EE) atomicAdd(&g_deg[dst[e]], 1);
}

__global__ void k_scan() {
    __shared__ int part[1024];
    const int t = threadIdx.x;
    const int CH = (NN + 1023) / 1024;  // 49
    int beg = t * CH;
    int end = beg + CH; if (end > NN) end = NN;
    int s = 0;
    for (int i = beg; i < end; i++) s += g_deg[i];
    part[t] = s;
    __syncthreads();
    for (int off = 1; off < 1024; off <<= 1) {
        int v = (t >= off) ? part[t - off] : 0;
        __syncthreads();
        part[t] += v;
        __syncthreads();
    }
    int ex = (t == 0) ? 0 : part[t - 1];
    for (int i = beg; i < end; i++) {
        g_rowptr[i] = ex;
        g_cursor[i] = ex;
        ex += g_deg[i];
    }
    if (t == 0) g_rowptr[NN] = part[1023];
}

__global__ void k_scatter(const int* __restrict__ src, const int* __restrict__ dst) {
    int e = blockIdx.x * blockDim.x + threadIdx.x;
    if (e < EE) {
        int d = dst[e];
        int pos = atomicAdd(&g_cursor[d], 1);
        g_colsrc[pos] = src[e];
    }
}

// ---------------- GAT linear: h = [featA, featH] @ W (NG gates), + el/er epilogue ----------------
// W points to gate0 of this call, layout [gate][fin][64]. al/ar point to gate0 row (64 floats per gate).
// hout layout: [row][g*64 + c].
template <int NG>
__global__ void gemm_gat(const float* __restrict__ featA, int fA,
                         const float* __restrict__ featH,
                         const float* __restrict__ W,
                         const float* __restrict__ al, const float* __restrict__ ar,
                         float* __restrict__ hout,
                         float* __restrict__ el0, float* __restrict__ er0,
                         float* __restrict__ el1, float* __restrict__ er1,
                         int fin) {
    extern __shared__ float sm[];
    const int LDW = NG * 64;
    float* Wsh = sm;                 // fin * LDW
    float* fsh = sm + fin * LDW;     // 32 * fin
    const int tid = threadIdx.x;
    const int lane = tid & 31;
    const int w = tid >> 5;

    // stage W (once per block)
    for (int i = tid; i < fin * LDW; i += blockDim.x) {
        int k = i / LDW;
        int cc = i - k * LDW;
        int g = cc >> 6, c = cc & 63;
        Wsh[i] = W[(g * fin + k) * 64 + c];
    }

    // preload attention vectors (per-lane 2 cols per gate)
    float alv[NG][2], arv[NG][2];
#pragma unroll
    for (int g = 0; g < NG; g++) {
        alv[g][0] = al[g * 64 + 2 * lane];
        alv[g][1] = al[g * 64 + 2 * lane + 1];
        arv[g][0] = ar[g * 64 + 2 * lane];
        arv[g][1] = ar[g * 64 + 2 * lane + 1];
    }

    for (int row0 = blockIdx.x * 32; row0 < NN; row0 += gridDim.x * 32) {
        __syncthreads();
        // stage 32 feature rows: [featA | featH]
        for (int i = tid; i < 32 * 64; i += blockDim.x) {
            int r = i >> 6, c = i & 63;
            int row = row0 + r;
            fsh[r * fin + fA + c] = (row < NN) ? featH[row * 64 + c] : 0.f;
        }
        for (int i = tid; i < 32 * fA; i += blockDim.x) {
            int r = i / fA, c = i - r * fA;
            int row = row0 + r;
            fsh[r * fin + c] = (row < NN) ? featA[row * fA + c] : 0.f;
        }
        __syncthreads();

        const int r0 = w * 4;
        float acc[4][2 * NG];
#pragma unroll
        for (int r = 0; r < 4; r++)
#pragma unroll
            for (int j = 0; j < 2 * NG; j++) acc[r][j] = 0.f;

#pragma unroll 2
        for (int k = 0; k < fin; k++) {
            float2 w0 = *(const float2*)(Wsh + k * LDW + 2 * lane);
            float2 w1;
            if (NG == 2) w1 = *(const float2*)(Wsh + k * LDW + 64 + 2 * lane);
#pragma unroll
            for (int r = 0; r < 4; r++) {
                float f = fsh[(r0 + r) * fin + k];
                acc[r][0] = fmaf(f, w0.x, acc[r][0]);
                acc[r][1] = fmaf(f, w0.y, acc[r][1]);
                if (NG == 2) {
                    acc[r][2] = fmaf(f, w1.x, acc[r][2]);
                    acc[r][3] = fmaf(f, w1.y, acc[r][3]);
                }
            }
        }

        // epilogue: write h, reduce el/er
#pragma unroll
        for (int r = 0; r < 4; r++) {
            int row = row0 + r0 + r;
            float pel0 = acc[r][0] * alv[0][0] + acc[r][1] * alv[0][1];
            float per0 = acc[r][0] * arv[0][0] + acc[r][1] * arv[0][1];
            float pel1 = 0.f, per1 = 0.f;
            if (NG == 2) {
                pel1 = acc[r][2] * alv[1][0] + acc[r][3] * alv[1][1];
                per1 = acc[r][2] * arv[1][0] + acc[r][3] * arv[1][1];
            }
#pragma unroll
            for (int off = 16; off > 0; off >>= 1) {
                pel0 += __shfl_xor_sync(0xffffffffu, pel0, off);
                per0 += __shfl_xor_sync(0xffffffffu, per0, off);
                if (NG == 2) {
                    pel1 += __shfl_xor_sync(0xffffffffu, pel1, off);
                    per1 += __shfl_xor_sync(0xffffffffu, per1, off);
                }
            }
            if (row < NN) {
                float2 v0 = make_float2(acc[r][0], acc[r][1]);
                *(float2*)&hout[(size_t)row * LDW + 2 * lane] = v0;
                if (NG == 2) {
                    float2 v1 = make_float2(acc[r][2], acc[r][3]);
                    *(float2*)&hout[(size_t)row * LDW + 64 + 2 * lane] = v1;
                }
                if (lane == 0) {
                    el0[row] = pel0;
                    er0[row] = per0;
                    if (NG == 2) { el1[row] = pel1; er1[row] = per1; }
                }
            }
        }
    }
}

// ---------------- edge softmax + aggregation, warp per destination ----------------
template <int NG>
__global__ void agg_gat(const float* __restrict__ h,
                        const float* __restrict__ el0, const float* __restrict__ er0,
                        const float* __restrict__ el1, const float* __restrict__ er1,
                        float* __restrict__ outp) {
    int wid = (blockIdx.x * blockDim.x + threadIdx.x) >> 5;
    if (wid >= NN) return;
    const int lane = threadIdx.x & 31;
    const int d = wid;
    const int beg = g_rowptr[d];
    const int end = g_rowptr[d + 1];

    const float er0d = er0[d];
    const float er1d = (NG == 2) ? er1[d] : 0.f;

    // pass 1: stable-softmax max per gate
    float m0 = -1e30f, m1 = -1e30f;
    for (int j = beg + lane; j < end; j += 32) {
        int s = g_colsrc[j];
        float e0 = el0[s] + er0d; e0 = e0 > 0.f ? e0 : 0.2f * e0;
        m0 = fmaxf(m0, e0);
        if (NG == 2) {
            float e1 = el1[s] + er1d; e1 = e1 > 0.f ? e1 : 0.2f * e1;
            m1 = fmaxf(m1, e1);
        }
    }
#pragma unroll
    for (int off = 16; off > 0; off >>= 1) {
        m0 = fmaxf(m0, __shfl_xor_sync(0xffffffffu, m0, off));
        if (NG == 2) m1 = fmaxf(m1, __shfl_xor_sync(0xffffffffu, m1, off));
    }

    // pass 2: exp-weighted aggregate
    const int HT = NG * 64;
    const int VEC = HT / 32;  // 4 (NG=2) or 2 (NG=1)
    float acc0 = 0.f, acc1 = 0.f, acc2 = 0.f, acc3 = 0.f;
    float sum0 = 0.f, sum1 = 0.f;
    const int base = lane * VEC;
    const bool useg1 = (NG == 2) && (base >= 64);

    for (int j = beg; j < end; j++) {
        int s = g_colsrc[j];  // warp-uniform broadcast
        float e0 = el0[s] + er0d; e0 = e0 > 0.f ? e0 : 0.2f * e0;
        float ex0 = __expf(e0 - m0);
        sum0 += ex0;
        float wgt = ex0;
        if (NG == 2) {
            float e1 = el1[s] + er1d; e1 = e1 > 0.f ? e1 : 0.2f * e1;
            float ex1 = __expf(e1 - m1);
            sum1 += ex1;
            if (useg1) wgt = ex1;
        }
        const float* hp = h + (size_t)s * HT + base;
        if (VEC == 4) {
            float4 v = *(const float4*)hp;
            acc0 = fmaf(wgt, v.x, acc0);
            acc1 = fmaf(wgt, v.y, acc1);
            acc2 = fmaf(wgt, v.z, acc2);
            acc3 = fmaf(wgt, v.w, acc3);
        } else {
            float2 v = *(const float2*)hp;
            acc0 = fmaf(wgt, v.x, acc0);
            acc1 = fmaf(wgt, v.y, acc1);
        }
    }

    float ssel = useg1 ? sum1 : sum0;
    float inv = 1.f / fmaxf(ssel, 1e-9f);
    float* op = outp + (size_t)d * HT + base;
    if (VEC == 4) {
        float4 o = make_float4(acc0 * inv, acc1 * inv, acc2 * inv, acc3 * inv);
        *(float4*)op = o;
    } else {
        float2 o = make_float2(acc0 * inv, acc1 * inv);
        *(float2*)op = o;
    }
}

// ---------------- GRU elementwise ----------------
__device__ __forceinline__ float sigmoidf_(float x) { return 1.f / (1.f + __expf(-x)); }

__global__ void k_gates(const float* __restrict__ prerz, const float* __restrict__ b,
                        const float* __restrict__ hx,
                        float* __restrict__ zb, float* __restrict__ rh) {
    int i = blockIdx.x * blockDim.x + threadIdx.x;
    if (i >= NN * HH) return;
    int row = i >> 6, c = i & 63;
    float r = sigmoidf_(prerz[(size_t)row * 128 + c] + b[c]);
    float z = sigmoidf_(prerz[(size_t)row * 128 + 64 + c] + b[64 + c]);
    zb[i] = z;
    rh[i] = r * hx[i];
}

__global__ void k_hnew(const float* __restrict__ prec, const float* __restrict__ b2,
                       const float* __restrict__ zb, float* __restrict__ hx) {
    int i = blockIdx.x * blockDim.x + threadIdx.x;
    if (i >= NN * HH) return;
    int c = i & 63;
    float hc = tanhf(prec[i] + b2[c]);
    float z = zb[i];
    hx[i] = z * hx[i] + (1.f - z) * hc;
}

// ---------------- projection ----------------
__global__ void k_proj(const float* __restrict__ hfinal, const float* __restrict__ pW,
                       const float* __restrict__ pb,
                       float* __restrict__ outslice, float* __restrict__ decin) {
    int row = blockIdx.x * blockDim.x + threadIdx.x;
    if (row >= NN) return;
    float o0 = pb[0], o1 = pb[1];
    const float* hr = hfinal + (size_t)row * 64;
#pragma unroll
    for (int c = 0; c < 64; c++) {
        float v = hr[c];
        o0 = fmaf(v, pW[2 * c], o0);
        o1 = fmaf(v, pW[2 * c + 1], o1);
    }
    outslice[2 * row] = o0;
    outslice[2 * row + 1] = o1;
    decin[2 * row] = o0;
    decin[2 * row + 1] = o1;
}

// ---------------- host orchestration ----------------
struct DevPtrs {
    int *deg, *rowptr, *cursor, *colsrc;
    float *h0, *h1, *hrz, *hc, *el0, *el1, *er0, *er1;
    float *prerz, *prec, *zbuf, *rh, *decin;
};

static void get_ptrs(DevPtrs& P) {
    cudaGetSymbolAddress((void**)&P.deg, g_deg);
    cudaGetSymbolAddress((void**)&P.rowptr, g_rowptr);
    cudaGetSymbolAddress((void**)&P.cursor, g_cursor);
    cudaGetSymbolAddress((void**)&P.colsrc, g_colsrc);
    cudaGetSymbolAddress((void**)&P.h0, g_h0);
    cudaGetSymbolAddress((void**)&P.h1, g_h1);
    cudaGetSymbolAddress((void**)&P.hrz, g_hrz);
    cudaGetSymbolAddress((void**)&P.hc, g_hc);
    cudaGetSymbolAddress((void**)&P.el0, g_el0);
    cudaGetSymbolAddress((void**)&P.el1, g_el1);
    cudaGetSymbolAddress((void**)&P.er0, g_er0);
    cudaGetSymbolAddress((void**)&P.er1, g_er1);
    cudaGetSymbolAddress((void**)&P.prerz, g_prerz);
    cudaGetSymbolAddress((void**)&P.prec, g_prec);
    cudaGetSymbolAddress((void**)&P.zbuf, g_zbuf);
    cudaGetSymbolAddress((void**)&P.rh, g_rh);
    cudaGetSymbolAddress((void**)&P.decin, g_decin);
}

static void gru_cell(const DevPtrs& P,
                     const float* featA, int fA, float* hx,
                     const float* W, const float* al, const float* ar, const float* b) {
    const int fin = fA + HH;
    const size_t smem2 = (size_t)(fin * 128 + 32 * fin) * sizeof(float);
    const size_t smem1 = (size_t)(fin * 64 + 32 * fin) * sizeof(float);
    const int aggBlocks = (NN * 32 + 255) / 256;   // warp per dst
    const int ewBlocks = (NN * HH + 255) / 256;

    // r and z gates (fused)
    gemm_gat<2><<<296, 256, smem2>>>(featA, fA, hx, W, al, ar,
                                     P.hrz, P.el0, P.er0, P.el1, P.er1, fin);
    agg_gat<2><<<aggBlocks, 256>>>(P.hrz, P.el0, P.er0, P.el1, P.er1, P.prerz);
    k_gates<<<ewBlocks, 256>>>(P.prerz, b, hx, P.zbuf, P.rh);

    // candidate gate
    gemm_gat<1><<<296, 256, smem1>>>(featA, fA, P.rh, W + (size_t)2 * fin * HH,
                                     al + 128, ar + 128,
                                     P.hc, P.el0, P.er0, nullptr, nullptr, fin);
    agg_gat<1><<<aggBlocks, 256>>>(P.hc, P.el0, P.er0, nullptr, nullptr, P.prec);
    k_hnew<<<ewBlocks, 256>>>(P.prec, b + 128, P.zbuf, hx);
}

extern "C" void kernel_launch(void* const* d_in, const int* in_sizes, int n_in,
                              void* d_out, int out_size) {
    (void)in_sizes; (void)n_in;
    const float* x = (const float*)d_in[0];
    const int* src = (const int*)d_in[1];
    const int* dst = (const int*)d_in[2];
    const float* enc_W0 = (const float*)d_in[3];
    const float* enc_al0 = (const float*)d_in[4];
    const float* enc_ar0 = (const float*)d_in[5];
    const float* enc_b0 = (const float*)d_in[6];
    const float* enc_W1 = (const float*)d_in[7];
    const float* enc_al1 = (const float*)d_in[8];
    const float* enc_ar1 = (const float*)d_in[9];
    const float* enc_b1 = (const float*)d_in[10];
    const float* dec_W0 = (const float*)d_in[11];
    const float* dec_al0 = (const float*)d_in[12];
    const float* dec_ar0 = (const float*)d_in[13];
    const float* dec_b0 = (const float*)d_in[14];
    const float* dec_W1 = (const float*)d_in[15];
    const float* dec_al1 = (const float*)d_in[16];
    const float* dec_ar1 = (const float*)d_in[17];
    const float* dec_b1 = (const float*)d_in[18];
    const float* proj_W = (const float*)d_in[19];
    const float* proj_b = (const float*)d_in[20];
    float* out = (float*)d_out;
    (void)out_size;

    cudaFuncSetAttribute(gemm_gat<2>, cudaFuncAttributeMaxDynamicSharedMemorySize, 84 * 1024);
    cudaFuncSetAttribute(gemm_gat<1>, cudaFuncAttributeMaxDynamicSharedMemorySize, 52 * 1024);

    DevPtrs P;
    get_ptrs(P);

    const int ewBlocks = (NN * HH + 255) / 256;
    const int eBlocks = (EE + 255) / 256;

    // zero state
    k_zero_f<<<ewBlocks, 256>>>(P.h0, NN * HH);
    k_zero_f<<<ewBlocks, 256>>>(P.h1, NN * HH);
    k_zero_f<<<(NN * DD + 255) / 256, 256>>>(P.decin, NN * DD);

    // CSR build (dst-sorted edge list)
    k_zero_i<<<(NN + 255) / 256, 256>>>(P.deg, NN);
    k_hist<<<eBlocks, 256>>>(dst);
    k_scan<<<1, 1024>>>();
    k_scatter<<<eBlocks, 256>>>(src, dst);

    // encoder
    for (int t = 0; t < TT; t++) {
        const float* xt = x + (size_t)t * NN * FF;
        gru_cell(P, xt, FF, P.h0, enc_W0, enc_al0, enc_ar0, enc_b0);
        gru_cell(P, P.h0, HH, P.h1, enc_W1, enc_al1, enc_ar1, enc_b1);
    }

    // decoder
    for (int t = 0; t < HZ; t++) {
        gru_cell(P, P.decin, DD, P.h0, dec_W0, dec_al0, dec_ar0, dec_b0);
        gru_cell(P, P.h0, HH, P.h1, dec_W1, dec_al1, dec_ar1, dec_b1);
        k_proj<<<(NN + 255) / 256, 256>>>(P.h1, proj_W, proj_b,
                                          out + (size_t)t * NN * DD, P.decin);
    }
}

// round 2
// speedup vs baseline: 1.4711x; 1.4711x over previous
#include <cuda_runtime.h>
#include <cuda_bf16.h>
#include <math.h>

// Problem constants
#define NN 50000
#define EE 800000
#define FF 2
#define DD 2
#define HH 64
#define TT 12
#define HZ 12

// ---------------- scratch (static device globals; no allocation) ----------------
__device__ __align__(256) int   g_deg[NN];
__device__ __align__(256) int   g_rowptr[NN + 1];
__device__ __align__(256) int   g_cursor[NN];
__device__ __align__(256) int   g_colsrc[EE];
__device__ __align__(256) float g_h0[NN * HH];
__device__ __align__(256) float g_h1[NN * HH];
__device__ __align__(256) float g_hrz[NN * 2 * HH];
__device__ __align__(256) float g_hc[NN * HH];
__device__ __align__(256) float g_el2[NN * 2];
__device__ __align__(256) float g_er2[NN * 2];
__device__ __align__(256) float g_el0[NN];
__device__ __align__(256) float g_er0[NN];
__device__ __align__(256) float g_zbuf[NN * HH];
__device__ __align__(256) float g_rh[NN * HH];
__device__ __align__(256) float g_decin[NN * DD];

// ---------------- f32x2 packed-FMA helpers ----------------
__device__ __forceinline__ unsigned long long pack2(float x) {
    unsigned long long r;
    asm("mov.b64 %0, {%1, %1};" : "=l"(r) : "f"(x));
    return r;
}
__device__ __forceinline__ void ffma2(unsigned long long& d, unsigned long long a,
                                      unsigned long long b) {
    asm("fma.rn.f32x2 %0, %1, %2, %0;" : "+l"(d) : "l"(a), "l"(b));
}
__device__ __forceinline__ float2 unpack2(unsigned long long v) {
    float2 f;
    asm("mov.b64 {%0, %1}, %2;" : "=f"(f.x), "=f"(f.y) : "l"(v));
    return f;
}

// ---------------- small utility kernels ----------------
__global__ void k_zero_f(float* p, int n) {
    int i = blockIdx.x * blockDim.x + threadIdx.x;
    if (i < n) p[i] = 0.f;
}
__global__ void k_zero_i(int* p, int n) {
    int i = blockIdx.x * blockDim.x + threadIdx.x;
    if (i < n) p[i] = 0;
}

// ---------------- CSR build ----------------
__global__ void k_hist(const int* __restrict__ dst) {
    int e = blockIdx.x * blockDim.x + threadIdx.x;
    if (e < EE) atomicAdd(&g_deg[dst[e]], 1);
}

__global__ void k_scan() {
    __shared__ int part[1024];
    const int t = threadIdx.x;
    const int CH = (NN + 1023) / 1024;
    int beg = t * CH;
    int end = beg + CH; if (end > NN) end = NN;
    int s = 0;
    for (int i = beg; i < end; i++) s += g_deg[i];
    part[t] = s;
    __syncthreads();
    for (int off = 1; off < 1024; off <<= 1) {
        int v = (t >= off) ? part[t - off] : 0;
        __syncthreads();
        part[t] += v;
        __syncthreads();
    }
    int ex = (t == 0) ? 0 : part[t - 1];
    for (int i = beg; i < end; i++) {
        g_rowptr[i] = ex;
        g_cursor[i] = ex;
        ex += g_deg[i];
    }
    if (t == 0) g_rowptr[NN] = part[1023];
}

__global__ void k_scatter(const int* __restrict__ src, const int* __restrict__ dst) {
    int e = blockIdx.x * blockDim.x + threadIdx.x;
    if (e < EE) {
        int d = dst[e];
        int pos = atomicAdd(&g_cursor[d], 1);
        g_colsrc[pos] = src[e];
    }
}

// ---------------- GAT linear (register-tiled SGEMM, f32x2 packed FMA) ----------------
// Computes h = [featA | featH] @ W for NG gates fused (N = NG*64 output cols),
// with attention logits el/er reduced in the epilogue.
// W layout: [gate][fin][64].   hout: [row][N].   elp/erp: [row][NG].
template <int NG>
__global__ __launch_bounds__(256, 2)
void gemm_gat(const float* __restrict__ featA, int fA,
              const float* __restrict__ featH,
              const float* __restrict__ W,
              const float* __restrict__ al, const float* __restrict__ ar,
              float* __restrict__ hout,
              float* __restrict__ elp, float* __restrict__ erp,
              int fin, int kpad) {
    constexpr int N = NG * 64;
    constexpr int CG = N / 8;        // col-groups (8 cols each): 16 or 8
    constexpr int RPT = CG / 2;      // rows per thread: 8 or 4
    constexpr int FSTR = 132;        // fsh row stride (bank-conflict pad)

    extern __shared__ float sm[];
    float* Wsh = sm;                 // [kpad][N]
    float* fsh = sm + kpad * N;      // [16][FSTR]

    const int tid = threadIdx.x;
    const int cg = tid % CG;
    const int rg = tid / CG;
    const int lane = tid & 31;

    // stage full W (zero-pad k >= fin)
    for (int idx = tid; idx < kpad * N; idx += 256) {
        int k = idx / N, c = idx - k * N;
        int g = c >> 6, ci = c & 63;
        Wsh[idx] = (k < fin) ? W[(size_t)(g * fin + k) * 64 + ci] : 0.f;
    }

    // per-thread attention vectors (8 cols of one gate)
    float alv[8], arv[8];
#pragma unroll
    for (int i = 0; i < 8; i++) {
        alv[i] = al[cg * 8 + i];
        arv[i] = ar[cg * 8 + i];
    }

    const int row0 = blockIdx.x * 128;

    unsigned long long acc[RPT][4];
#pragma unroll
    for (int r = 0; r < RPT; r++)
#pragma unroll
        for (int p = 0; p < 4; p++) acc[r][p] = 0ull;

    for (int kc = 0; kc < kpad; kc += 16) {
        __syncthreads();
        // stage 16 x 128 feature chunk, transposed: fsh[k][row]
#pragma unroll
        for (int u = 0; u < 2; u++) {
            int idx = tid + u * 256;         // 0..511
            int r = idx >> 2, kq = idx & 3;
            int grow = row0 + r;
#pragma unroll
            for (int j = 0; j < 4; j++) {
                int kk = kc + kq * 4 + j;
                float v = 0.f;
                if (grow < NN && kk < fin)
                    v = (kk < fA) ? featA[(size_t)grow * fA + kk]
                                  : featH[(size_t)grow * 64 + (kk - fA)];
                fsh[(kq * 4 + j) * FSTR + r] = v;
            }
        }
        __syncthreads();

#pragma unroll
        for (int k = 0; k < 16; k++) {
            const float* fr = fsh + k * FSTR + rg * RPT;
            const ulonglong2* wp = (const ulonglong2*)(Wsh + (size_t)(kc + k) * N + cg * 8);
            ulonglong2 wA = wp[0];
            ulonglong2 wB = wp[1];
            float a[RPT];
            {
                float4 a0 = *(const float4*)fr;
                a[0] = a0.x; a[1] = a0.y; a[2] = a0.z; a[3] = a0.w;
                if (RPT == 8) {
                    float4 a1 = *(const float4*)(fr + 4);
                    a[4] = a1.x; a[5] = a1.y; a[6] = a1.z; a[7] = a1.w;
                }
            }
#pragma unroll
            for (int r = 0; r < RPT; r++) {
                unsigned long long ap = pack2(a[r]);
                ffma2(acc[r][0], ap, wA.x);
                ffma2(acc[r][1], ap, wA.y);
                ffma2(acc[r][2], ap, wB.x);
                ffma2(acc[r][3], ap, wB.y);
            }
        }
    }

    // epilogue: unpack, attention-logit reduce, store
#pragma unroll
    for (int r = 0; r < RPT; r++) {
        int row = row0 + rg * RPT + r;
        float f[8];
#pragma unroll
        for (int p = 0; p < 4; p++) {
            float2 v = unpack2(acc[r][p]);
            f[2 * p] = v.x;
            f[2 * p + 1] = v.y;
        }
        float pe = 0.f, pr = 0.f;
#pragma unroll
        for (int i = 0; i < 8; i++) {
            pe = fmaf(f[i], alv[i], pe);
            pr = fmaf(f[i], arv[i], pr);
        }
        // reduce across the 8 col-groups of this row's gate (8-lane groups)
#pragma unroll
        for (int off = 1; off < 8; off <<= 1) {
            pe += __shfl_xor_sync(0xffffffffu, pe, off);
            pr += __shfl_xor_sync(0xffffffffu, pr, off);
        }
        if (row < NN) {
            float* hp = hout + (size_t)row * N + cg * 8;
            *(float4*)hp = make_float4(f[0], f[1], f[2], f[3]);
            *(float4*)(hp + 4) = make_float4(f[4], f[5], f[6], f[7]);
            if ((cg & 7) == 0) {
                int g = cg >> 3;
                elp[row * NG + g] = pe;
                erp[row * NG + g] = pr;
            }
        }
        (void)lane;
    }
}

// ---------------- r/z aggregation + fused GRU gate elementwise ----------------
// warp per destination. h: [row][128] (r cols 0-63, z cols 64-127).
// Writes rh = sigmoid(agg_r + b_r) * hx  and  zbuf = sigmoid(agg_z + b_z).
__global__ void agg_rz(const float* __restrict__ h,
                       const float2* __restrict__ el2, const float2* __restrict__ er2,
                       const float* __restrict__ b,
                       const float* __restrict__ hx,
                       float* __restrict__ rh, float* __restrict__ zbuf) {
    int wid = (blockIdx.x * blockDim.x + threadIdx.x) >> 5;
    if (wid >= NN) return;
    const int lane = threadIdx.x & 31;
    const int beg = g_rowptr[wid];
    const int end = g_rowptr[wid + 1];
    const float2 er = er2[wid];
    const int base = lane * 4;
    const bool gz = lane >= 16;   // z-gate lanes

    float sum0 = 0.f, sum1 = 0.f;
    float a0 = 0.f, a1 = 0.f, a2 = 0.f, a3 = 0.f;

    for (int j0 = beg; j0 < end; j0 += 32) {
        int jj = j0 + lane;
        int sv = 0;
        float w0v = 0.f, w1v = 0.f;
        if (jj < end) {
            sv = g_colsrc[jj];
            float2 ev = el2[sv];
            float e0 = ev.x + er.x; e0 = e0 > 0.f ? e0 : 0.2f * e0;
            float e1 = ev.y + er.y; e1 = e1 > 0.f ? e1 : 0.2f * e1;
            w0v = __expf(e0);
            w1v = __expf(e1);
        }
        int cnt = end - j0; if (cnt > 32) cnt = 32;
#pragma unroll 4
        for (int i = 0; i < cnt; i++) {
            int s = __shfl_sync(0xffffffffu, sv, i);
            float w0 = __shfl_sync(0xffffffffu, w0v, i);
            float w1 = __shfl_sync(0xffffffffu, w1v, i);
            sum0 += w0;
            sum1 += w1;
            float wg = gz ? w1 : w0;
            float4 v = *(const float4*)(h + (size_t)s * 128 + base);
            a0 = fmaf(wg, v.x, a0);
            a1 = fmaf(wg, v.y, a1);
            a2 = fmaf(wg, v.z, a2);
            a3 = fmaf(wg, v.w, a3);
        }
    }

    float inv = 1.f / fmaxf(gz ? sum1 : sum0, 1e-9f);
    float g0 = 1.f / (1.f + __expf(-(a0 * inv + b[base])));
    float g1 = 1.f / (1.f + __expf(-(a1 * inv + b[base + 1])));
    float g2 = 1.f / (1.f + __expf(-(a2 * inv + b[base + 2])));
    float g3 = 1.f / (1.f + __expf(-(a3 * inv + b[base + 3])));
    if (!gz) {
        float4 hv = *(const float4*)(hx + (size_t)wid * 64 + base);
        *(float4*)(rh + (size_t)wid * 64 + base) =
            make_float4(g0 * hv.x, g1 * hv.y, g2 * hv.z, g3 * hv.w);
    } else {
        *(float4*)(zbuf + (size_t)wid * 64 + (base - 64)) = make_float4(g0, g1, g2, g3);
    }
}

// ---------------- candidate aggregation + fused GRU state update ----------------
// h: [row][64]. hx updated in place: h' = z*hx + (1-z)*tanh(agg + b).
__global__ void agg_c(const float* __restrict__ h,
                      const float* __restrict__ el, const float* __restrict__ er,
                      const float* __restrict__ b2,
                      const float* __restrict__ zbuf,
                      float* __restrict__ hx) {
    int wid = (blockIdx.x * blockDim.x + threadIdx.x) >> 5;
    if (wid >= NN) return;
    const int lane = threadIdx.x & 31;
    const int beg = g_rowptr[wid];
    const int end = g_rowptr[wid + 1];
    const float erd = er[wid];
    const int base = lane * 2;

    float sum = 0.f;
    float a0 = 0.f, a1 = 0.f;

    for (int j0 = beg; j0 < end; j0 += 32) {
        int jj = j0 + lane;
        int sv = 0;
        float wv = 0.f;
        if (jj < end) {
            sv = g_colsrc[jj];
            float e = el[sv] + erd; e = e > 0.f ? e : 0.2f * e;
            wv = __expf(e);
        }
        int cnt = end - j0; if (cnt > 32) cnt = 32;
#pragma unroll 4
        for (int i = 0; i < cnt; i++) {
            int s = __shfl_sync(0xffffffffu, sv, i);
            float w = __shfl_sync(0xffffffffu, wv, i);
            sum += w;
            float2 v = *(const float2*)(h + (size_t)s * 64 + base);
            a0 = fmaf(w, v.x, a0);
            a1 = fmaf(w, v.y, a1);
        }
    }

    float inv = 1.f / fmaxf(sum, 1e-9f);
    float hc0 = tanhf(a0 * inv + b2[base]);
    float hc1 = tanhf(a1 * inv + b2[base + 1]);
    float2 z = *(const float2*)(zbuf + (size_t)wid * 64 + base);
    float2 hv = *(const float2*)(hx + (size_t)wid * 64 + base);
    float n0 = z.x * hv.x + (1.f - z.x) * hc0;
    float n1 = z.y * hv.y + (1.f - z.y) * hc1;
    *(float2*)(hx + (size_t)wid * 64 + base) = make_float2(n0, n1);
}

// ---------------- projection ----------------
__global__ void k_proj(const float* __restrict__ hfinal, const float* __restrict__ pW,
                       const float* __restrict__ pb,
                       float* __restrict__ outslice, float* __restrict__ decin) {
    int row = blockIdx.x * blockDim.x + threadIdx.x;
    if (row >= NN) return;
    float o0 = pb[0], o1 = pb[1];
    const float* hr = hfinal + (size_t)row * 64;
#pragma unroll
    for (int c = 0; c < 64; c++) {
        float v = hr[c];
        o0 = fmaf(v, pW[2 * c], o0);
        o1 = fmaf(v, pW[2 * c + 1], o1);
    }
    outslice[2 * row] = o0;
    outslice[2 * row + 1] = o1;
    decin[2 * row] = o0;
    decin[2 * row + 1] = o1;
}

// ---------------- host orchestration ----------------
struct DevPtrs {
    int *deg, *rowptr, *cursor, *colsrc;
    float *h0, *h1, *hrz, *hc, *el2, *er2, *el0, *er0;
    float *zbuf, *rh, *decin;
};

static void get_ptrs(DevPtrs& P) {
    cudaGetSymbolAddress((void**)&P.deg, g_deg);
    cudaGetSymbolAddress((void**)&P.rowptr, g_rowptr);
    cudaGetSymbolAddress((void**)&P.cursor, g_cursor);
    cudaGetSymbolAddress((void**)&P.colsrc, g_colsrc);
    cudaGetSymbolAddress((void**)&P.h0, g_h0);
    cudaGetSymbolAddress((void**)&P.h1, g_h1);
    cudaGetSymbolAddress((void**)&P.hrz, g_hrz);
    cudaGetSymbolAddress((void**)&P.hc, g_hc);
    cudaGetSymbolAddress((void**)&P.el2, g_el2);
    cudaGetSymbolAddress((void**)&P.er2, g_er2);
    cudaGetSymbolAddress((void**)&P.el0, g_el0);
    cudaGetSymbolAddress((void**)&P.er0, g_er0);
    cudaGetSymbolAddress((void**)&P.zbuf, g_zbuf);
    cudaGetSymbolAddress((void**)&P.rh, g_rh);
    cudaGetSymbolAddress((void**)&P.decin, g_decin);
}

static void gru_cell(const DevPtrs& P,
                     const float* featA, int fA, float* hx,
                     const float* W, const float* al, const float* ar, const float* b) {
    const int fin = fA + HH;
    const int kpad = (fin + 15) & ~15;
    const size_t smem2 = (size_t)(kpad * 128 + 16 * 132) * sizeof(float);
    const size_t smem1 = (size_t)(kpad * 64 + 16 * 132) * sizeof(float);
    const int gemmBlocks = (NN + 127) / 128;   // 391
    const int aggBlocks = (NN + 7) / 8;        // warp per dst, 8 warps/block

    // r + z gates (fused GEMM + fused agg/gate elementwise)
    gemm_gat<2><<<gemmBlocks, 256, smem2>>>(featA, fA, hx, W, al, ar,
                                            P.hrz, P.el2, P.er2, fin, kpad);
    agg_rz<<<aggBlocks, 256>>>(P.hrz, (const float2*)P.el2, (const float2*)P.er2,
                               b, hx, P.rh, P.zbuf);

    // candidate gate + fused state update
    gemm_gat<1><<<gemmBlocks, 256, smem1>>>(featA, fA, P.rh, W + (size_t)2 * fin * HH,
                                            al + 128, ar + 128,
                                            P.hc, P.el0, P.er0, fin, kpad);
    agg_c<<<aggBlocks, 256>>>(P.hc, P.el0, P.er0, b + 128, P.zbuf, hx);
}

extern "C" void kernel_launch(void* const* d_in, const int* in_sizes, int n_in,
                              void* d_out, int out_size) {
    (void)in_sizes; (void)n_in;
    const float* x = (const float*)d_in[0];
    const int* src = (const int*)d_in[1];
    const int* dst = (const int*)d_in[2];
    const float* enc_W0 = (const float*)d_in[3];
    const float* enc_al0 = (const float*)d_in[4];
    const float* enc_ar0 = (const float*)d_in[5];
    const float* enc_b0 = (const float*)d_in[6];
    const float* enc_W1 = (const float*)d_in[7];
    const float* enc_al1 = (const float*)d_in[8];
    const float* enc_ar1 = (const float*)d_in[9];
    const float* enc_b1 = (const float*)d_in[10];
    const float* dec_W0 = (const float*)d_in[11];
    const float* dec_al0 = (const float*)d_in[12];
    const float* dec_ar0 = (const float*)d_in[13];
    const float* dec_b0 = (const float*)d_in[14];
    const float* dec_W1 = (const float*)d_in[15];
    const float* dec_al1 = (const float*)d_in[16];
    const float* dec_ar1 = (const float*)d_in[17];
    const float* dec_b1 = (const float*)d_in[18];
    const float* proj_W = (const float*)d_in[19];
    const float* proj_b = (const float*)d_in[20];
    float* out = (float*)d_out;
    (void)out_size;

    cudaFuncSetAttribute(gemm_gat<2>, cudaFuncAttributeMaxDynamicSharedMemorySize, 100 * 1024);
    cudaFuncSetAttribute(gemm_gat<1>, cudaFuncAttributeMaxDynamicSharedMemorySize, 64 * 1024);

    DevPtrs P;
    get_ptrs(P);

    const int ewBlocks = (NN * HH + 255) / 256;
    const int eBlocks = (EE + 255) / 256;

    // zero state
    k_zero_f<<<ewBlocks, 256>>>(P.h0, NN * HH);
    k_zero_f<<<ewBlocks, 256>>>(P.h1, NN * HH);
    k_zero_f<<<(NN * DD + 255) / 256, 256>>>(P.decin, NN * DD);

    // CSR build (dst-sorted edge list)
    k_zero_i<<<(NN + 255) / 256, 256>>>(P.deg, NN);
    k_hist<<<eBlocks, 256>>>(dst);
    k_scan<<<1, 1024>>>();
    k_scatter<<<eBlocks, 256>>>(src, dst);

    // encoder
    for (int t = 0; t < TT; t++) {
        const float* xt = x + (size_t)t * NN * FF;
        gru_cell(P, xt, FF, P.h0, enc_W0, enc_al0, enc_ar0, enc_b0);
        gru_cell(P, P.h0, HH, P.h1, enc_W1, enc_al1, enc_ar1, enc_b1);
    }

    // decoder
    for (int t = 0; t < HZ; t++) {
        gru_cell(P, P.decin, DD, P.h0, dec_W0, dec_al0, dec_ar0, dec_b0);
        gru_cell(P, P.h0, HH, P.h1, dec_W1, dec_al1, dec_ar1, dec_b1);
        k_proj<<<(NN + 255) / 256, 256>>>(P.h1, proj_W, proj_b,
                                          out + (size_t)t * NN * DD, P.decin);
    }
}

// round 3
// speedup vs baseline: 1.6956x; 1.1526x over previous
#include <cuda_runtime.h>
#include <cuda_fp16.h>
#include <math.h>

// Problem constants
#define NN 50000
#define EE 800000
#define FF 2
#define DD 2
#define HH 64
#define TT 12
#define HZ 12

// ---------------- scratch (static device globals; no allocation) ----------------
__device__ __align__(256) int    g_deg[NN];
__device__ __align__(256) int    g_rowptr[NN + 1];
__device__ __align__(256) int    g_cursor[NN];
__device__ __align__(256) int    g_colsrc[EE];
__device__ __align__(256) float  g_h0[NN * HH];
__device__ __align__(256) float  g_h1[NN * HH];
__device__ __align__(256) __half g_hrz[NN * 2 * HH];   // fp16 gather matrix (r|z)
__device__ __align__(256) __half g_hc[NN * HH];        // fp16 gather matrix (candidate)
__device__ __align__(256) float  g_el2[NN * 2];
__device__ __align__(256) float  g_er2[NN * 2];
__device__ __align__(256) float  g_el0[NN];
__device__ __align__(256) float  g_er0[NN];
__device__ __align__(256) float  g_zbuf[NN * HH];
__device__ __align__(256) float  g_rh[NN * HH];
__device__ __align__(256) float  g_decin[NN * DD];

// ---------------- f32x2 packed-FMA helpers ----------------
__device__ __forceinline__ unsigned long long pack2(float x) {
    unsigned long long r;
    asm("mov.b64 %0, {%1, %1};" : "=l"(r) : "f"(x));
    return r;
}
__device__ __forceinline__ void ffma2(unsigned long long& d, unsigned long long a,
                                      unsigned long long b) {
    asm("fma.rn.f32x2 %0, %1, %2, %0;" : "+l"(d) : "l"(a), "l"(b));
}
__device__ __forceinline__ float2 unpack2(unsigned long long v) {
    float2 f;
    asm("mov.b64 {%0, %1}, %2;" : "=f"(f.x), "=f"(f.y) : "l"(v));
    return f;
}

// ---------------- small utility kernels ----------------
__global__ void k_zero_f(float* p, int n) {
    int i = blockIdx.x * blockDim.x + threadIdx.x;
    if (i < n) p[i] = 0.f;
}
__global__ void k_zero_i(int* p, int n) {
    int i = blockIdx.x * blockDim.x + threadIdx.x;
    if (i < n) p[i] = 0;
}

// ---------------- CSR build ----------------
__global__ void k_hist(const int* __restrict__ dst) {
    int e = blockIdx.x * blockDim.x + threadIdx.x;
    if (e < EE) atomicAdd(&g_deg[dst[e]], 1);
}

__global__ void k_scan() {
    __shared__ int part[1024];
    const int t = threadIdx.x;
    const int CH = (NN + 1023) / 1024;
    int beg = t * CH;
    int end = beg + CH; if (end > NN) end = NN;
    int s = 0;
    for (int i = beg; i < end; i++) s += g_deg[i];
    part[t] = s;
    __syncthreads();
    for (int off = 1; off < 1024; off <<= 1) {
        int v = (t >= off) ? part[t - off] : 0;
        __syncthreads();
        part[t] += v;
        __syncthreads();
    }
    int ex = (t == 0) ? 0 : part[t - 1];
    for (int i = beg; i < end; i++) {
        g_rowptr[i] = ex;
        g_cursor[i] = ex;
        ex += g_deg[i];
    }
    if (t == 0) g_rowptr[NN] = part[1023];
}

__global__ void k_scatter(const int* __restrict__ src, const int* __restrict__ dst) {
    int e = blockIdx.x * blockDim.x + threadIdx.x;
    if (e < EE) {
        int d = dst[e];
        int pos = atomicAdd(&g_cursor[d], 1);
        g_colsrc[pos] = src[e];
    }
}

// ---------------- GAT linear (register-tiled SGEMM, f32x2 packed FMA) ----------------
// h = [featA | featH] @ W for NG gates fused (N = NG*64 cols), fp16 h output,
// attention logits el/er (fp32) reduced in the epilogue.
template <int NG>
__global__ __launch_bounds__(256, 2)
void gemm_gat(const float* __restrict__ featA, int fA,
              const float* __restrict__ featH,
              const float* __restrict__ W,
              const float* __restrict__ al, const float* __restrict__ ar,
              __half* __restrict__ hout,
              float* __restrict__ elp, float* __restrict__ erp,
              int fin, int kpad) {
    constexpr int N = NG * 64;
    constexpr int CG = N / 8;        // col-groups (8 cols each): 16 or 8
    constexpr int RPT = CG / 2;      // rows per thread: 8 or 4
    constexpr int FSTR = 132;        // fsh row stride (bank-conflict pad)

    extern __shared__ float sm[];
    float* Wsh = sm;                 // [kpad][N]
    float* fsh = sm + kpad * N;      // [16][FSTR]

    const int tid = threadIdx.x;
    const int cg = tid % CG;
    const int rg = tid / CG;

    for (int idx = tid; idx < kpad * N; idx += 256) {
        int k = idx / N, c = idx - k * N;
        int g = c >> 6, ci = c & 63;
        Wsh[idx] = (k < fin) ? W[(size_t)(g * fin + k) * 64 + ci] : 0.f;
    }

    float alv[8], arv[8];
#pragma unroll
    for (int i = 0; i < 8; i++) {
        alv[i] = al[cg * 8 + i];
        arv[i] = ar[cg * 8 + i];
    }

    const int row0 = blockIdx.x * 128;

    unsigned long long acc[RPT][4];
#pragma unroll
    for (int r = 0; r < RPT; r++)
#pragma unroll
        for (int p = 0; p < 4; p++) acc[r][p] = 0ull;

    for (int kc = 0; kc < kpad; kc += 16) {
        __syncthreads();
#pragma unroll
        for (int u = 0; u < 2; u++) {
            int idx = tid + u * 256;
            int r = idx >> 2, kq = idx & 3;
            int grow = row0 + r;
#pragma unroll
            for (int j = 0; j < 4; j++) {
                int kk = kc + kq * 4 + j;
                float v = 0.f;
                if (grow < NN && kk < fin)
                    v = (kk < fA) ? featA[(size_t)grow * fA + kk]
                                  : featH[(size_t)grow * 64 + (kk - fA)];
                fsh[(kq * 4 + j) * FSTR + r] = v;
            }
        }
        __syncthreads();

#pragma unroll
        for (int k = 0; k < 16; k++) {
            const float* fr = fsh + k * FSTR + rg * RPT;
            const ulonglong2* wp = (const ulonglong2*)(Wsh + (size_t)(kc + k) * N + cg * 8);
            ulonglong2 wA = wp[0];
            ulonglong2 wB = wp[1];
            float a[RPT];
            {
                float4 a0 = *(const float4*)fr;
                a[0] = a0.x; a[1] = a0.y; a[2] = a0.z; a[3] = a0.w;
                if (RPT == 8) {
                    float4 a1 = *(const float4*)(fr + 4);
                    a[4] = a1.x; a[5] = a1.y; a[6] = a1.z; a[7] = a1.w;
                }
            }
#pragma unroll
            for (int r = 0; r < RPT; r++) {
                unsigned long long ap = pack2(a[r]);
                ffma2(acc[r][0], ap, wA.x);
                ffma2(acc[r][1], ap, wA.y);
                ffma2(acc[r][2], ap, wB.x);
                ffma2(acc[r][3], ap, wB.y);
            }
        }
    }

    // epilogue: unpack, attention-logit reduce (fp32), store h as fp16
#pragma unroll
    for (int r = 0; r < RPT; r++) {
        int row = row0 + rg * RPT + r;
        float f[8];
#pragma unroll
        for (int p = 0; p < 4; p++) {
            float2 v = unpack2(acc[r][p]);
            f[2 * p] = v.x;
            f[2 * p + 1] = v.y;
        }
        float pe = 0.f, pr = 0.f;
#pragma unroll
        for (int i = 0; i < 8; i++) {
            pe = fmaf(f[i], alv[i], pe);
            pr = fmaf(f[i], arv[i], pr);
        }
#pragma unroll
        for (int off = 1; off < 8; off <<= 1) {
            pe += __shfl_xor_sync(0xffffffffu, pe, off);
            pr += __shfl_xor_sync(0xffffffffu, pr, off);
        }
        if (row < NN) {
            __half2 h01 = __floats2half2_rn(f[0], f[1]);
            __half2 h23 = __floats2half2_rn(f[2], f[3]);
            __half2 h45 = __floats2half2_rn(f[4], f[5]);
            __half2 h67 = __floats2half2_rn(f[6], f[7]);
            uint4 st;
            st.x = *(unsigned*)&h01;
            st.y = *(unsigned*)&h23;
            st.z = *(unsigned*)&h45;
            st.w = *(unsigned*)&h67;
            *(uint4*)(hout + (size_t)row * N + cg * 8) = st;
            if ((cg & 7) == 0) {
                int g = cg >> 3;
                elp[row * NG + g] = pe;
                erp[row * NG + g] = pr;
            }
        }
    }
}

// ---------------- r/z aggregation + fused GRU gate elementwise ----------------
// warp per destination. h: fp16 [row][128] (r cols 0-63, z cols 64-127).
__global__ void agg_rz(const __half2* __restrict__ h,
                       const float2* __restrict__ el2, const float2* __restrict__ er2,
                       const float* __restrict__ b,
                       const float* __restrict__ hx,
                       float* __restrict__ rh, float* __restrict__ zbuf) {
    int wid = (blockIdx.x * blockDim.x + threadIdx.x) >> 5;
    if (wid >= NN) return;
    const int lane = threadIdx.x & 31;
    const int beg = g_rowptr[wid];
    const int end = g_rowptr[wid + 1];
    const float2 er = er2[wid];
    const int base = lane * 4;        // fp32-col base (0..124)
    const bool gz = lane >= 16;       // z-gate lanes

    float sum0 = 0.f, sum1 = 0.f;
    float a0 = 0.f, a1 = 0.f, a2 = 0.f, a3 = 0.f;

    for (int j0 = beg; j0 < end; j0 += 32) {
        int jj = j0 + lane;
        int sv = 0;
        float w0v = 0.f, w1v = 0.f;
        if (jj < end) {
            sv = g_colsrc[jj];
            float2 ev = el2[sv];
            float e0 = ev.x + er.x; e0 = e0 > 0.f ? e0 : 0.2f * e0;
            float e1 = ev.y + er.y; e1 = e1 > 0.f ? e1 : 0.2f * e1;
            w0v = __expf(e0);
            w1v = __expf(e1);
        }
        int cnt = end - j0; if (cnt > 32) cnt = 32;
#pragma unroll 4
        for (int i = 0; i < cnt; i++) {
            int s = __shfl_sync(0xffffffffu, sv, i);
            float w0 = __shfl_sync(0xffffffffu, w0v, i);
            float w1 = __shfl_sync(0xffffffffu, w1v, i);
            sum0 += w0;
            sum1 += w1;
            float wg = gz ? w1 : w0;
            uint2 u = *(const uint2*)(h + (size_t)s * 64 + lane * 2);
            float2 v0 = __half22float2(*(__half2*)&u.x);
            float2 v1 = __half22float2(*(__half2*)&u.y);
            a0 = fmaf(wg, v0.x, a0);
            a1 = fmaf(wg, v0.y, a1);
            a2 = fmaf(wg, v1.x, a2);
            a3 = fmaf(wg, v1.y, a3);
        }
    }

    float inv = 1.f / fmaxf(gz ? sum1 : sum0, 1e-9f);
    float g0 = 1.f / (1.f + __expf(-(a0 * inv + b[base])));
    float g1 = 1.f / (1.f + __expf(-(a1 * inv + b[base + 1])));
    float g2 = 1.f / (1.f + __expf(-(a2 * inv + b[base + 2])));
    float g3 = 1.f / (1.f + __expf(-(a3 * inv + b[base + 3])));
    if (!gz) {
        float4 hv = *(const float4*)(hx + (size_t)wid * 64 + base);
        *(float4*)(rh + (size_t)wid * 64 + base) =
            make_float4(g0 * hv.x, g1 * hv.y, g2 * hv.z, g3 * hv.w);
    } else {
        *(float4*)(zbuf + (size_t)wid * 64 + (base - 64)) = make_float4(g0, g1, g2, g3);
    }
}

// ---------------- candidate aggregation + fused GRU update (+ optional proj) --------
// h: fp16 [row][64]. hx updated in place; if PROJ, also out = h' @ proj_W + proj_b.
template <bool PROJ>
__global__ void agg_c(const __half2* __restrict__ h,
                      const float* __restrict__ el, const float* __restrict__ er,
                      const float* __restrict__ b2,
                      const float* __restrict__ zbuf,
                      float* __restrict__ hx,
                      const float* __restrict__ pW, const float* __restrict__ pb,
                      float* __restrict__ outslice, float* __restrict__ decin) {
    int wid = (blockIdx.x * blockDim.x + threadIdx.x) >> 5;
    if (wid >= NN) return;
    const int lane = threadIdx.x & 31;
    const int beg = g_rowptr[wid];
    const int end = g_rowptr[wid + 1];
    const float erd = er[wid];
    const int base = lane * 2;

    float sum = 0.f;
    float a0 = 0.f, a1 = 0.f;

    for (int j0 = beg; j0 < end; j0 += 32) {
        int jj = j0 + lane;
        int sv = 0;
        float wv = 0.f;
        if (jj < end) {
            sv = g_colsrc[jj];
            float e = el[sv] + erd; e = e > 0.f ? e : 0.2f * e;
            wv = __expf(e);
        }
        int cnt = end - j0; if (cnt > 32) cnt = 32;
#pragma unroll 4
        for (int i = 0; i < cnt; i++) {
            int s = __shfl_sync(0xffffffffu, sv, i);
            float w = __shfl_sync(0xffffffffu, wv, i);
            sum += w;
            __half2 p = h[(size_t)s * 32 + lane];
            float2 v = __half22float2(p);
            a0 = fmaf(w, v.x, a0);
            a1 = fmaf(w, v.y, a1);
        }
    }

    float inv = 1.f / fmaxf(sum, 1e-9f);
    float hc0 = tanhf(a0 * inv + b2[base]);
    float hc1 = tanhf(a1 * inv + b2[base + 1]);
    float2 z = *(const float2*)(zbuf + (size_t)wid * 64 + base);
    float2 hv = *(const float2*)(hx + (size_t)wid * 64 + base);
    float n0 = z.x * hv.x + (1.f - z.x) * hc0;
    float n1 = z.y * hv.y + (1.f - z.y) * hc1;
    *(float2*)(hx + (size_t)wid * 64 + base) = make_float2(n0, n1);

    if (PROJ) {
        float o0 = n0 * pW[2 * base] + n1 * pW[2 * base + 2];
        float o1 = n0 * pW[2 * base + 1] + n1 * pW[2 * base + 3];
#pragma unroll
        for (int off = 16; off > 0; off >>= 1) {
            o0 += __shfl_xor_sync(0xffffffffu, o0, off);
            o1 += __shfl_xor_sync(0xffffffffu, o1, off);
        }
        if (lane == 0) {
            o0 += pb[0];
            o1 += pb[1];
            outslice[2 * wid] = o0;
            outslice[2 * wid + 1] = o1;
            decin[2 * wid] = o0;
            decin[2 * wid + 1] = o1;
        }
    }
}

// ---------------- host orchestration ----------------
struct DevPtrs {
    int *deg, *rowptr, *cursor, *colsrc;
    float *h0, *h1, *el2, *er2, *el0, *er0;
    __half *hrz, *hc;
    float *zbuf, *rh, *decin;
};

static void get_ptrs(DevPtrs& P) {
    cudaGetSymbolAddress((void**)&P.deg, g_deg);
    cudaGetSymbolAddress((void**)&P.rowptr, g_rowptr);
    cudaGetSymbolAddress((void**)&P.cursor, g_cursor);
    cudaGetSymbolAddress((void**)&P.colsrc, g_colsrc);
    cudaGetSymbolAddress((void**)&P.h0, g_h0);
    cudaGetSymbolAddress((void**)&P.h1, g_h1);
    cudaGetSymbolAddress((void**)&P.hrz, g_hrz);
    cudaGetSymbolAddress((void**)&P.hc, g_hc);
    cudaGetSymbolAddress((void**)&P.el2, g_el2);
    cudaGetSymbolAddress((void**)&P.er2, g_er2);
    cudaGetSymbolAddress((void**)&P.el0, g_el0);
    cudaGetSymbolAddress((void**)&P.er0, g_er0);
    cudaGetSymbolAddress((void**)&P.zbuf, g_zbuf);
    cudaGetSymbolAddress((void**)&P.rh, g_rh);
    cudaGetSymbolAddress((void**)&P.decin, g_decin);
}

static void gru_cell(const DevPtrs& P,
                     const float* featA, int fA, float* hx,
                     const float* W, const float* al, const float* ar, const float* b,
                     const float* pW = nullptr, const float* pb = nullptr,
                     float* outslice = nullptr) {
    const int fin = fA + HH;
    const int kpad = (fin + 15) & ~15;
    const size_t smem2 = (size_t)(kpad * 128 + 16 * 132) * sizeof(float);
    const size_t smem1 = (size_t)(kpad * 64 + 16 * 132) * sizeof(float);
    const int gemmBlocks = (NN + 127) / 128;
    const int aggBlocks = (NN + 7) / 8;

    gemm_gat<2><<<gemmBlocks, 256, smem2>>>(featA, fA, hx, W, al, ar,
                                            P.hrz, P.el2, P.er2, fin, kpad);
    agg_rz<<<aggBlocks, 256>>>((const __half2*)P.hrz, (const float2*)P.el2,
                               (const float2*)P.er2, b, hx, P.rh, P.zbuf);

    gemm_gat<1><<<gemmBlocks, 256, smem1>>>(featA, fA, P.rh, W + (size_t)2 * fin * HH,
                                            al + 128, ar + 128,
                                            P.hc, P.el0, P.er0, fin, kpad);
    if (outslice) {
        agg_c<true><<<aggBlocks, 256>>>((const __half2*)P.hc, P.el0, P.er0, b + 128,
                                        P.zbuf, hx, pW, pb, outslice, P.decin);
    } else {
        agg_c<false><<<aggBlocks, 256>>>((const __half2*)P.hc, P.el0, P.er0, b + 128,
                                         P.zbuf, hx, nullptr, nullptr, nullptr, nullptr);
    }
}

extern "C" void kernel_launch(void* const* d_in, const int* in_sizes, int n_in,
                              void* d_out, int out_size) {
    (void)in_sizes; (void)n_in;
    const float* x = (const float*)d_in[0];
    const int* src = (const int*)d_in[1];
    const int* dst = (const int*)d_in[2];
    const float* enc_W0 = (const float*)d_in[3];
    const float* enc_al0 = (const float*)d_in[4];
    const float* enc_ar0 = (const float*)d_in[5];
    const float* enc_b0 = (const float*)d_in[6];
    const float* enc_W1 = (const float*)d_in[7];
    const float* enc_al1 = (const float*)d_in[8];
    const float* enc_ar1 = (const float*)d_in[9];
    const float* enc_b1 = (const float*)d_in[10];
    const float* dec_W0 = (const float*)d_in[11];
    const float* dec_al0 = (const float*)d_in[12];
    const float* dec_ar0 = (const float*)d_in[13];
    const float* dec_b0 = (const float*)d_in[14];
    const float* dec_W1 = (const float*)d_in[15];
    const float* dec_al1 = (const float*)d_in[16];
    const float* dec_ar1 = (const float*)d_in[17];
    const float* dec_b1 = (const float*)d_in[18];
    const float* proj_W = (const float*)d_in[19];
    const float* proj_b = (const float*)d_in[20];
    float* out = (float*)d_out;
    (void)out_size;

    cudaFuncSetAttribute(gemm_gat<2>, cudaFuncAttributeMaxDynamicSharedMemorySize, 100 * 1024);
    cudaFuncSetAttribute(gemm_gat<1>, cudaFuncAttributeMaxDynamicSharedMemorySize, 64 * 1024);

    DevPtrs P;
    get_ptrs(P);

    const int ewBlocks = (NN * HH + 255) / 256;
    const int eBlocks = (EE + 255) / 256;

    // CSR build first, then zero h0, so launch #6 (ncu -s 5 -c 1) is gemm_gat<2>.
    k_zero_i<<<(NN + 255) / 256, 256>>>(P.deg, NN);                 // 1
    k_hist<<<eBlocks, 256>>>(dst);                                  // 2
    k_scan<<<1, 1024>>>();                                          // 3
    k_scatter<<<eBlocks, 256>>>(src, dst);                          // 4
    k_zero_f<<<ewBlocks, 256>>>(P.h0, NN * HH);                     // 5

    // encoder t=0, layer 1 (its first launch, gemm_gat<2>, is #6 -> profiled)
    gru_cell(P, x, FF, P.h0, enc_W0, enc_al0, enc_ar0, enc_b0);

    // deferred state zeroing (needed before their first consumers)
    k_zero_f<<<ewBlocks, 256>>>(P.h1, NN * HH);
    k_zero_f<<<(NN * DD + 255) / 256, 256>>>(P.decin, NN * DD);

    gru_cell(P, P.h0, HH, P.h1, enc_W1, enc_al1, enc_ar1, enc_b1);

    for (int t = 1; t < TT; t++) {
        const float* xt = x + (size_t)t * NN * FF;
        gru_cell(P, xt, FF, P.h0, enc_W0, enc_al0, enc_ar0, enc_b0);
        gru_cell(P, P.h0, HH, P.h1, enc_W1, enc_al1, enc_ar1, enc_b1);
    }

    // decoder (projection fused into layer-2 candidate aggregation)
    for (int t = 0; t < HZ; t++) {
        gru_cell(P, P.decin, DD, P.h0, dec_W0, dec_al0, dec_ar0, dec_b0);
        gru_cell(P, P.h0, HH, P.h1, dec_W1, dec_al1, dec_ar1, dec_b1,
                 proj_W, proj_b, out + (size_t)t * NN * DD);
    }
}